// round 16
// baseline (speedup 1.0000x reference)
#include <cuda_runtime.h>
#include <cuda_fp16.h>
#include <math.h>
#include <stdint.h>

#define N_PTS 2000000
#define N_CLU 65536
#define N_GRPS (N_PTS / 16)
#define GRP 4
#define WPB 8
#define PT_BLOCKS ((N_GRPS + WPB * GRP - 1) / (WPB * GRP))

__device__ float  g_agg[N_CLU * 64];
__device__ __half g_midh[N_CLU * 128];
__device__ int    g_cnt[N_CLU];
__device__ int    g_cur[N_CLU];
__device__ int    g_bsum[64];
__device__ int    g_perm[N_PTS];
__device__ int    g_slbl[N_PTS];
__device__ __align__(32) __half g_xh[(size_t)N_PTS * 16];  // sorted fp16 inputs

// ---------------------------------------------------------------------------
__device__ __forceinline__ void red2(float* p, float a, float b) {
    asm volatile("red.global.add.v2.f32 [%0],{%1,%2};" :: "l"(p), "f"(a), "f"(b) : "memory");
}
__device__ __forceinline__ uint32_t h2u(float lo, float hi) {
    __half2 h = __floats2half2_rn(lo, hi);
    return *reinterpret_cast<uint32_t*>(&h);
}
__device__ __forceinline__ void mma16816_acc(float* d, const uint32_t* a, const uint32_t* b) {
    asm volatile("mma.sync.aligned.m16n8k16.row.col.f32.f16.f16.f32 "
        "{%0,%1,%2,%3},{%4,%5,%6,%7},{%8,%9},{%0,%1,%2,%3};"
        : "+f"(d[0]), "+f"(d[1]), "+f"(d[2]), "+f"(d[3])
        : "r"(a[0]), "r"(a[1]), "r"(a[2]), "r"(a[3]), "r"(b[0]), "r"(b[1]));
}
__device__ __forceinline__ void mma1688_acc(float* d, const uint32_t* a, uint32_t b) {
    asm volatile("mma.sync.aligned.m16n8k8.row.col.f32.f16.f16.f32 "
        "{%0,%1,%2,%3},{%4,%5},{%6},{%0,%1,%2,%3};"
        : "+f"(d[0]), "+f"(d[1]), "+f"(d[2]), "+f"(d[3])
        : "r"(a[0]), "r"(a[1]), "r"(b));
}

// ---------------------------------------------------------------------------
// fused zero + counting sort (indices only) + fp16 gather
// ---------------------------------------------------------------------------
#define ZAGG4 (N_CLU * 64 / 4)
#define ZCNT4 (N_CLU / 4)
__global__ void k_zero() {
    int i = blockIdx.x * 256 + threadIdx.x;
    if (i < ZAGG4) ((float4*)g_agg)[i] = make_float4(0.f, 0.f, 0.f, 0.f);
    else if (i < ZAGG4 + ZCNT4) ((int4*)g_cnt)[i - ZAGG4] = make_int4(0, 0, 0, 0);
}
__global__ void k_hist(const int* __restrict__ labels) {
    int i = blockIdx.x * 256 + threadIdx.x;
    if (i < N_PTS) atomicAdd(&g_cnt[labels[i]], 1);
}
__global__ __launch_bounds__(256) void k_scan1() {
    __shared__ int sp[256];
    int t = threadIdx.x, b = blockIdx.x;
    int base = b * 1024 + t * 4;
    int4 c = *(const int4*)(g_cnt + base);
    int sum = c.x + c.y + c.z + c.w;
    sp[t] = sum;
    __syncthreads();
    for (int o = 1; o < 256; o <<= 1) {
        int v = (t >= o) ? sp[t - o] : 0;
        __syncthreads();
        sp[t] += v;
        __syncthreads();
    }
    int excl = sp[t] - sum;
    int4 ov;
    ov.x = excl; ov.y = excl + c.x; ov.z = ov.y + c.y; ov.w = ov.z + c.z;
    *(int4*)(g_cur + base) = ov;
    if (t == 255) g_bsum[b] = sp[255];
}
__global__ void k_scan2() {
    __shared__ int sp[64];
    int t = threadIdx.x;
    int v = g_bsum[t];
    sp[t] = v;
    __syncthreads();
    for (int o = 1; o < 64; o <<= 1) {
        int u = (t >= o) ? sp[t - o] : 0;
        __syncthreads();
        sp[t] += u;
        __syncthreads();
    }
    g_bsum[t] = sp[t] - v;
}
__global__ void k_scatter(const int* __restrict__ labels) {
    int i = blockIdx.x * 256 + threadIdx.x;
    if (i >= N_PTS) return;
    int l = labels[i];
    int pos = atomicAdd(&g_cur[l], 1) + g_bsum[l >> 10];
    g_perm[pos] = i;
    g_slbl[pos] = l;
}
__global__ void k_gather(const float* __restrict__ pf,
                         const float* __restrict__ pts,
                         const float* __restrict__ cc) {
    int pos = blockIdx.x * 256 + threadIdx.x;
    if (pos >= N_PTS) return;
    int i = g_perm[pos];
    int l = g_slbl[pos];
    float4 v0 = ((const float4*)pf)[(size_t)i * 2];
    float4 v1 = ((const float4*)pf)[(size_t)i * 2 + 1];
    float d0 = cc[(size_t)l * 3 + 0] - pts[(size_t)i * 3 + 0];
    float d1 = cc[(size_t)l * 3 + 1] - pts[(size_t)i * 3 + 1];
    float d2 = cc[(size_t)l * 3 + 2] - pts[(size_t)i * 3 + 2];
    uint4* dst = (uint4*)(g_xh + (size_t)pos * 16);
    dst[0] = make_uint4(h2u(v0.x, v0.y), h2u(v0.z, v0.w),
                        h2u(v1.x, v1.y), h2u(v1.z, v1.w));
    dst[1] = make_uint4(h2u(d0, d1), h2u(d2, 0.f), 0u, 0u);
}

// ---------------------------------------------------------------------------
// k_point: tensor-core MLP, TWO groups interleaved per iteration for mma ILP.
// Large B-fragments in block-shared memory (no spills). GRP=4 for small tail.
// ---------------------------------------------------------------------------
__global__ __launch_bounds__(256, 2) void k_point(
    const float* __restrict__ we0, const float* __restrict__ be0,
    const float* __restrict__ we1, const float* __restrict__ be1,
    const float* __restrict__ we2, const float* __restrict__ be2,
    const float* __restrict__ we3, const float* __restrict__ be3,
    const float* __restrict__ wa0, const float* __restrict__ ba0,
    const float* __restrict__ wa1, const float* __restrict__ ba1)
{
    __shared__ float stp[WPB][16 * 72];
    __shared__ int   slb[WPB][32];
    __shared__ __align__(16) uint2 sBA[8][32];
    __shared__ __align__(16) uint2 sL3a[8][32];
    __shared__ __align__(16) uint2 sL3b[8][32];

    const int lane = threadIdx.x & 31;
    const int wid  = threadIdx.x >> 5;
    const int g    = lane >> 2;
    const int k0   = (lane & 3) * 2;

    float* W = stp[wid];

    if (wid == 0) {
#pragma unroll
        for (int t = 0; t < 8; t++) {
            int n = t * 8 + g;
            sBA[t][lane] = make_uint2(
                h2u(wa0[k0 * 64 + n], wa0[(k0 + 1) * 64 + n]),
                h2u(k0 + 8 < 11 ? wa0[(k0 + 8) * 64 + n] : 0.f,
                    k0 + 9 < 11 ? wa0[(k0 + 9) * 64 + n] : 0.f));
            sL3a[t][lane] = make_uint2(
                h2u(we3[k0 * 64 + n],       we3[(k0 + 1) * 64 + n]),
                h2u(we3[(k0 + 8) * 64 + n], we3[(k0 + 9) * 64 + n]));
            sL3b[t][lane] = make_uint2(
                h2u(we3[(k0 + 16) * 64 + n], we3[(k0 + 17) * 64 + n]),
                h2u(we3[(k0 + 24) * 64 + n], we3[(k0 + 25) * 64 + n]));
        }
    }

    uint32_t bE0[2];
    {
        int n = g;
        bE0[0] = h2u(we0[k0 * 8 + n], we0[(k0 + 1) * 8 + n]);
        bE0[1] = h2u(k0 + 8 < 11 ? we0[(k0 + 8) * 8 + n] : 0.f,
                     k0 + 9 < 11 ? we0[(k0 + 9) * 8 + n] : 0.f);
    }
    uint32_t bE1[2];
#pragma unroll
    for (int t = 0; t < 2; t++) {
        int n = t * 8 + g;
        bE1[t] = h2u(we1[k0 * 16 + n], we1[(k0 + 1) * 16 + n]);
    }
    uint32_t bE2[4][2];
#pragma unroll
    for (int t = 0; t < 4; t++) {
        int n = t * 8 + g;
        bE2[t][0] = h2u(we2[k0 * 32 + n], we2[(k0 + 1) * 32 + n]);
        bE2[t][1] = h2u(we2[(k0 + 8) * 32 + n], we2[(k0 + 9) * 32 + n]);
    }
    const float ba1s = ba1[0];
    __syncthreads();

    const int grp0 = (blockIdx.x * WPB + wid) * GRP;

#pragma unroll 1
    for (int it = 0; it < GRP; it += 2) {
        const int grpA = grp0 + it;
        const bool vA = (grpA < N_GRPS);
        const bool vB = (grpA + 1 < N_GRPS);
        if (!vA) break;
        const int pos0 = grpA * 16;

        __syncwarp();
        {
            int src = pos0 + lane;
            slb[wid][lane] = g_slbl[vB ? src : (lane < 16 ? src : pos0)];
        }

        uint32_t axA[4], axB[4];
        {
            const __half* r1 = g_xh + (size_t)(pos0 + g) * 16;
            const __half* r2 = g_xh + (size_t)(pos0 + g + 8) * 16;
            axA[0] = *(const uint32_t*)(r1 + k0);
            axA[1] = *(const uint32_t*)(r2 + k0);
            axA[2] = *(const uint32_t*)(r1 + k0 + 8);
            axA[3] = *(const uint32_t*)(r2 + k0 + 8);
            const size_t offB = vB ? 16 : 0;
            const __half* r3 = g_xh + (size_t)(pos0 + offB + g) * 16;
            const __half* r4 = g_xh + (size_t)(pos0 + offB + g + 8) * 16;
            axB[0] = *(const uint32_t*)(r3 + k0);
            axB[1] = *(const uint32_t*)(r4 + k0);
            axB[2] = *(const uint32_t*)(r3 + k0 + 8);
            axB[3] = *(const uint32_t*)(r4 + k0 + 8);
        }
        __syncwarp();

        // ----- attention (both groups interleaved) -----
        float aaA = 0.f, abA = 0.f, aaB = 0.f, abB = 0.f;
#pragma unroll
        for (int t = 0; t < 8; t++) {
            float b0 = ba0[t * 8 + k0], b1v = ba0[t * 8 + k0 + 1];
            float dA[4] = {b0, b1v, b0, b1v};
            float dB[4] = {b0, b1v, b0, b1v};
            uint2 bb = sBA[t][lane];
            mma16816_acc(dA, axA, (const uint32_t*)&bb);
            mma16816_acc(dB, axB, (const uint32_t*)&bb);
            float w0 = wa1[t * 8 + k0], w1 = wa1[t * 8 + k0 + 1];
            aaA += fmaxf(dA[0], 0.f) * w0 + fmaxf(dA[1], 0.f) * w1;
            abA += fmaxf(dA[2], 0.f) * w0 + fmaxf(dA[3], 0.f) * w1;
            aaB += fmaxf(dB[0], 0.f) * w0 + fmaxf(dB[1], 0.f) * w1;
            abB += fmaxf(dB[2], 0.f) * w0 + fmaxf(dB[3], 0.f) * w1;
        }
        aaA += __shfl_xor_sync(0xffffffffu, aaA, 1);
        aaA += __shfl_xor_sync(0xffffffffu, aaA, 2);
        abA += __shfl_xor_sync(0xffffffffu, abA, 1);
        abA += __shfl_xor_sync(0xffffffffu, abA, 2);
        aaB += __shfl_xor_sync(0xffffffffu, aaB, 1);
        aaB += __shfl_xor_sync(0xffffffffu, aaB, 2);
        abB += __shfl_xor_sync(0xffffffffu, abB, 1);
        abB += __shfl_xor_sync(0xffffffffu, abB, 2);
        const float aA0 = 1.f / (1.f + __expf(-(aaA + ba1s)));
        const float aA1 = 1.f / (1.f + __expf(-(abA + ba1s)));
        const float aB0 = 1.f / (1.f + __expf(-(aaB + ba1s)));
        const float aB1 = 1.f / (1.f + __expf(-(abB + ba1s)));

        // ----- L0 -----
        uint32_t h0A[2], h0B[2];
        {
            float b0 = be0[k0], b1v = be0[k0 + 1];
            float dA[4] = {b0, b1v, b0, b1v};
            float dB[4] = {b0, b1v, b0, b1v};
            mma16816_acc(dA, axA, bE0);
            mma16816_acc(dB, axB, bE0);
            h0A[0] = h2u(fmaxf(dA[0], 0.f), fmaxf(dA[1], 0.f));
            h0A[1] = h2u(fmaxf(dA[2], 0.f), fmaxf(dA[3], 0.f));
            h0B[0] = h2u(fmaxf(dB[0], 0.f), fmaxf(dB[1], 0.f));
            h0B[1] = h2u(fmaxf(dB[2], 0.f), fmaxf(dB[3], 0.f));
        }
        // ----- L1 -----
        uint32_t h1A[4], h1B[4];
#pragma unroll
        for (int t = 0; t < 2; t++) {
            float b0 = be1[t * 8 + k0], b1v = be1[t * 8 + k0 + 1];
            float dA[4] = {b0, b1v, b0, b1v};
            float dB[4] = {b0, b1v, b0, b1v};
            mma1688_acc(dA, h0A, bE1[t]);
            mma1688_acc(dB, h0B, bE1[t]);
            h1A[t * 2 + 0] = h2u(fmaxf(dA[0], 0.f), fmaxf(dA[1], 0.f));
            h1A[t * 2 + 1] = h2u(fmaxf(dA[2], 0.f), fmaxf(dA[3], 0.f));
            h1B[t * 2 + 0] = h2u(fmaxf(dB[0], 0.f), fmaxf(dB[1], 0.f));
            h1B[t * 2 + 1] = h2u(fmaxf(dB[2], 0.f), fmaxf(dB[3], 0.f));
        }
        // ----- L2 -----
        uint32_t h2aA[4], h2bA[4], h2aB[4], h2bB[4];
#pragma unroll
        for (int t = 0; t < 4; t++) {
            float b0 = be2[t * 8 + k0], b1v = be2[t * 8 + k0 + 1];
            float dA[4] = {b0, b1v, b0, b1v};
            float dB[4] = {b0, b1v, b0, b1v};
            mma16816_acc(dA, h1A, bE2[t]);
            mma16816_acc(dB, h1B, bE2[t]);
            uint32_t loA = h2u(fmaxf(dA[0], 0.f), fmaxf(dA[1], 0.f));
            uint32_t hiA = h2u(fmaxf(dA[2], 0.f), fmaxf(dA[3], 0.f));
            uint32_t loB = h2u(fmaxf(dB[0], 0.f), fmaxf(dB[1], 0.f));
            uint32_t hiB = h2u(fmaxf(dB[2], 0.f), fmaxf(dB[3], 0.f));
            if (t == 0)      { h2aA[0] = loA; h2aA[1] = hiA; h2aB[0] = loB; h2aB[1] = hiB; }
            else if (t == 1) { h2aA[2] = loA; h2aA[3] = hiA; h2aB[2] = loB; h2aB[3] = hiB; }
            else if (t == 2) { h2bA[0] = loA; h2bA[1] = hiA; h2bB[0] = loB; h2bB[1] = hiB; }
            else             { h2bA[2] = loA; h2bA[3] = hiA; h2bB[2] = loB; h2bB[3] = hiB; }
        }

        // ----- L3 + epilogue, group A then group B (W reused) -----
#pragma unroll 1
        for (int q = 0; q < 2; q++) {
            const uint32_t* h2a = q ? h2aB : h2aA;
            const uint32_t* h2b = q ? h2bB : h2bA;
            const float s0 = q ? aB0 : aA0;
            const float s1 = q ? aB1 : aA1;
            if (q && !vB) break;

#pragma unroll
            for (int t = 0; t < 8; t++) {
                float b0 = be3[t * 8 + k0], b1v = be3[t * 8 + k0 + 1];
                float d[4] = {b0, b1v, b0, b1v};
                uint2 wa = sL3a[t][lane];
                uint2 wb = sL3b[t][lane];
                mma16816_acc(d, h2a, (const uint32_t*)&wa);
                mma16816_acc(d, h2b, (const uint32_t*)&wb);
                float v0 = fmaxf(d[0], 0.f) * s0;
                float v1 = fmaxf(d[1], 0.f) * s0;
                float v2 = fmaxf(d[2], 0.f) * s1;
                float v3 = fmaxf(d[3], 0.f) * s1;
                *(float2*)(W + g * 72 + t * 8 + k0)       = make_float2(v0, v1);
                *(float2*)(W + (g + 8) * 72 + t * 8 + k0) = make_float2(v2, v3);
            }
            __syncwarp();

            {
                const int c0 = 2 * lane;
                const int lb0 = q * 16;
                int cur = slb[wid][lb0];
                float2 s = *(const float2*)(W + c0);
#pragma unroll 1
                for (int p = 1; p < 16; p++) {
                    int lb = slb[wid][lb0 + p];
                    float2 v = *(const float2*)(W + p * 72 + c0);
                    if (lb == cur) { s.x += v.x; s.y += v.y; }
                    else {
                        red2(g_agg + (size_t)cur * 64 + c0, s.x, s.y);
                        cur = lb; s = v;
                    }
                }
                red2(g_agg + (size_t)cur * 64 + c0, s.x, s.y);
            }
            __syncwarp();
        }
    }
}

// ---------------------------------------------------------------------------
// k_mid (tensor, smem-staged) — R14 version.
// ---------------------------------------------------------------------------
__global__ __launch_bounds__(256) void k_mid(
    const float* __restrict__ wo0, const float* __restrict__ bo0)
{
    __shared__ __align__(16) __half woT[128 * 68];
    __shared__ __align__(16) __half aH[128 * 68];
    __shared__ float sb[128];

    const int t = threadIdx.x;
    for (int i = t; i < 8192; i += 256) {
        int k = i >> 7, n = i & 127;
        woT[n * 68 + k] = __float2half(wo0[i]);
    }
    if (t < 128) sb[t] = bo0[t];
    const size_t base = (size_t)blockIdx.x * 128;
    for (int i = t; i < 8192; i += 256) {
        int row = i >> 6, k = i & 63;
        aH[row * 68 + k] = __float2half(g_agg[base * 64 + i]);
    }
    __syncthreads();

    const int lane = t & 31, w = t >> 5;
    const int g  = lane >> 2;
    const int k0 = (lane & 3) * 2;
    const int rA = w * 16 + g, rB = rA + 8;

    uint32_t a[4][4];
#pragma unroll
    for (int kk = 0; kk < 4; kk++) {
        a[kk][0] = *(const uint32_t*)(aH + rA * 68 + kk * 16 + k0);
        a[kk][1] = *(const uint32_t*)(aH + rB * 68 + kk * 16 + k0);
        a[kk][2] = *(const uint32_t*)(aH + rA * 68 + kk * 16 + k0 + 8);
        a[kk][3] = *(const uint32_t*)(aH + rB * 68 + kk * 16 + k0 + 8);
    }

#pragma unroll
    for (int tt = 0; tt < 16; tt++) {
        const int n = tt * 8;
        float b0 = sb[n + k0], b1 = sb[n + k0 + 1];
        float d[4] = {b0, b1, b0, b1};
#pragma unroll
        for (int kk = 0; kk < 4; kk++) {
            uint32_t bb[2];
            bb[0] = *(const uint32_t*)(woT + (n + g) * 68 + kk * 16 + k0);
            bb[1] = *(const uint32_t*)(woT + (n + g) * 68 + kk * 16 + k0 + 8);
            mma16816_acc(d, a[kk], bb);
        }
        *(uint32_t*)(g_midh + (base + rA) * 128 + n + k0) = h2u(fmaxf(d[0], 0.f), fmaxf(d[1], 0.f));
        *(uint32_t*)(g_midh + (base + rB) * 128 + n + k0) = h2u(fmaxf(d[2], 0.f), fmaxf(d[3], 0.f));
    }
}

// ---------------------------------------------------------------------------
// k_out (tensor, smem-staged) — R14 version.
// ---------------------------------------------------------------------------
__global__ __launch_bounds__(256) void k_out(
    const float* __restrict__ wo1, const float* __restrict__ bo1,
    float* __restrict__ out)
{
    extern __shared__ __align__(16) __half sh[];
    __half* aH  = sh;
    __half* woT = sh + 128 * 136;

    const int t  = threadIdx.x;
    const int mg = blockIdx.x >> 2;
    const int nb = (blockIdx.x & 3) * 64;
    const size_t base = (size_t)mg * 128;

    const uint32_t* gm32 = (const uint32_t*)(g_midh + base * 128);
    for (int i = t; i < 8192; i += 256) {
        int row = i >> 6, kp = i & 63;
        ((uint32_t*)(aH + row * 136))[kp] = gm32[i];
    }
    for (int i = t; i < 8192; i += 256) {
        int k = i >> 6, n = i & 63;
        woT[n * 136 + k] = __float2half(wo1[k * 256 + nb + n]);
    }
    __syncthreads();

    const int lane = t & 31, w = t >> 5;
    const int g  = lane >> 2;
    const int k0 = (lane & 3) * 2;
    const int rA = w * 16 + g, rB = rA + 8;

    uint32_t a[8][4];
#pragma unroll
    for (int kk = 0; kk < 8; kk++) {
        a[kk][0] = *(const uint32_t*)(aH + rA * 136 + kk * 16 + k0);
        a[kk][1] = *(const uint32_t*)(aH + rB * 136 + kk * 16 + k0);
        a[kk][2] = *(const uint32_t*)(aH + rA * 136 + kk * 16 + k0 + 8);
        a[kk][3] = *(const uint32_t*)(aH + rB * 136 + kk * 16 + k0 + 8);
    }

#pragma unroll
    for (int tt = 0; tt < 8; tt++) {
        const int n = tt * 8;
        float2 bb2 = *(const float2*)(bo1 + nb + n + k0);
        float d[4] = {bb2.x, bb2.y, bb2.x, bb2.y};
#pragma unroll
        for (int kk = 0; kk < 8; kk++) {
            uint32_t f[2];
            f[0] = *(const uint32_t*)(woT + (n + g) * 136 + kk * 16 + k0);
            f[1] = *(const uint32_t*)(woT + (n + g) * 136 + kk * 16 + k0 + 8);
            mma16816_acc(d, a[kk], f);
        }
        *(float2*)(out + (base + rA) * 256 + nb + n + k0) = make_float2(fmaxf(d[0], 0.f), fmaxf(d[1], 0.f));
        *(float2*)(out + (base + rB) * 256 + nb + n + k0) = make_float2(fmaxf(d[2], 0.f), fmaxf(d[3], 0.f));
    }
}

// ---------------------------------------------------------------------------
extern "C" void kernel_launch(void* const* d_in, const int* in_sizes, int n_in,
                              void* d_out, int out_size)
{
    const float* pf     = (const float*)d_in[0];
    const int*   labels = (const int*)  d_in[1];
    const float* cc     = (const float*)d_in[2];
    const float* pts    = (const float*)d_in[3];
    const float* we0    = (const float*)d_in[4];
    const float* be0    = (const float*)d_in[5];
    const float* we1    = (const float*)d_in[6];
    const float* be1    = (const float*)d_in[7];
    const float* we2    = (const float*)d_in[8];
    const float* be2    = (const float*)d_in[9];
    const float* we3    = (const float*)d_in[10];
    const float* be3    = (const float*)d_in[11];
    const float* wa0    = (const float*)d_in[12];
    const float* ba0    = (const float*)d_in[13];
    const float* wa1    = (const float*)d_in[14];
    const float* ba1    = (const float*)d_in[15];
    const float* wo0    = (const float*)d_in[16];
    const float* bo0    = (const float*)d_in[17];
    const float* wo1    = (const float*)d_in[18];
    const float* bo1    = (const float*)d_in[19];
    float* out = (float*)d_out;

    const int smem_out = (128 * 136 + 64 * 136) * 2;
    static int attr_set = 0;
    if (!attr_set) {
        cudaFuncSetAttribute(k_out, cudaFuncAttributeMaxDynamicSharedMemorySize, smem_out);
        attr_set = 1;
    }

    k_zero<<<(ZAGG4 + ZCNT4 + 255) / 256, 256>>>();
    k_hist<<<(N_PTS + 255) / 256, 256>>>(labels);
    k_scan1<<<64, 256>>>();
    k_scan2<<<1, 64>>>();
    k_scatter<<<(N_PTS + 255) / 256, 256>>>(labels);
    k_gather<<<(N_PTS + 255) / 256, 256>>>(pf, pts, cc);
    k_point<<<PT_BLOCKS, 256>>>(we0, be0, we1, be1, we2, be2, we3, be3,
                                wa0, ba0, wa1, ba1);
    k_mid<<<N_CLU / 128, 256>>>(wo0, bo0);
    k_out<<<(N_CLU / 128) * 4, 256, smem_out>>>(wo1, bo1, out);
}

// round 17
// speedup vs baseline: 1.1916x; 1.1916x over previous
#include <cuda_runtime.h>
#include <cuda_fp16.h>
#include <math.h>
#include <stdint.h>

#define N_PTS 2000000
#define N_CLU 65536
#define N_GRPS (N_PTS / 16)
#define GRP 8
#define WPB 8
#define PT_BLOCKS ((N_GRPS + WPB * GRP - 1) / (WPB * GRP))

__device__ float  g_agg[N_CLU * 64];
__device__ __half g_midh[N_CLU * 128];
__device__ int    g_cnt[N_CLU];
__device__ int    g_cur[N_CLU];
__device__ int    g_bsum[64];
__device__ int    g_slbl[N_PTS];
__device__ __align__(32) __half g_xh[(size_t)N_PTS * 16];  // sorted fp16 inputs

// ---------------------------------------------------------------------------
__device__ __forceinline__ void red2(float* p, float a, float b) {
    asm volatile("red.global.add.v2.f32 [%0],{%1,%2};" :: "l"(p), "f"(a), "f"(b) : "memory");
}
__device__ __forceinline__ uint32_t h2u(float lo, float hi) {
    __half2 h = __floats2half2_rn(lo, hi);
    return *reinterpret_cast<uint32_t*>(&h);
}
__device__ __forceinline__ void mma16816_acc(float* d, const uint32_t* a, const uint32_t* b) {
    asm volatile("mma.sync.aligned.m16n8k16.row.col.f32.f16.f16.f32 "
        "{%0,%1,%2,%3},{%4,%5,%6,%7},{%8,%9},{%0,%1,%2,%3};"
        : "+f"(d[0]), "+f"(d[1]), "+f"(d[2]), "+f"(d[3])
        : "r"(a[0]), "r"(a[1]), "r"(a[2]), "r"(a[3]), "r"(b[0]), "r"(b[1]));
}
__device__ __forceinline__ void mma1688_acc(float* d, const uint32_t* a, uint32_t b) {
    asm volatile("mma.sync.aligned.m16n8k8.row.col.f32.f16.f16.f32 "
        "{%0,%1,%2,%3},{%4,%5},{%6},{%0,%1,%2,%3};"
        : "+f"(d[0]), "+f"(d[1]), "+f"(d[2]), "+f"(d[3])
        : "r"(a[0]), "r"(a[1]), "r"(b));
}

// ---------------------------------------------------------------------------
// zero + counting sort; scatter MATERIALIZES fp16 inputs (32B aligned stores)
// ---------------------------------------------------------------------------
#define ZAGG4 (N_CLU * 64 / 4)
#define ZCNT4 (N_CLU / 4)
__global__ void k_zero() {
    int i = blockIdx.x * 256 + threadIdx.x;
    if (i < ZAGG4) ((float4*)g_agg)[i] = make_float4(0.f, 0.f, 0.f, 0.f);
    else if (i < ZAGG4 + ZCNT4) ((int4*)g_cnt)[i - ZAGG4] = make_int4(0, 0, 0, 0);
}
__global__ void k_hist(const int* __restrict__ labels) {
    int i = blockIdx.x * 256 + threadIdx.x;
    if (i < N_PTS) atomicAdd(&g_cnt[labels[i]], 1);
}
__global__ __launch_bounds__(256) void k_scan1() {
    __shared__ int sp[256];
    int t = threadIdx.x, b = blockIdx.x;
    int base = b * 1024 + t * 4;
    int4 c = *(const int4*)(g_cnt + base);
    int sum = c.x + c.y + c.z + c.w;
    sp[t] = sum;
    __syncthreads();
    for (int o = 1; o < 256; o <<= 1) {
        int v = (t >= o) ? sp[t - o] : 0;
        __syncthreads();
        sp[t] += v;
        __syncthreads();
    }
    int excl = sp[t] - sum;
    int4 ov;
    ov.x = excl; ov.y = excl + c.x; ov.z = ov.y + c.y; ov.w = ov.z + c.z;
    *(int4*)(g_cur + base) = ov;
    if (t == 255) g_bsum[b] = sp[255];
}
__global__ void k_scan2() {
    __shared__ int sp[64];
    int t = threadIdx.x;
    int v = g_bsum[t];
    sp[t] = v;
    __syncthreads();
    for (int o = 1; o < 64; o <<= 1) {
        int u = (t >= o) ? sp[t - o] : 0;
        __syncthreads();
        sp[t] += u;
        __syncthreads();
    }
    g_bsum[t] = sp[t] - v;
}
// scatter + materialize: coalesced fp32 reads, ONE aligned 32B random store
__global__ void k_scatter(const float* __restrict__ pf,
                          const float* __restrict__ pts,
                          const float* __restrict__ cc,
                          const int* __restrict__ labels) {
    int i = blockIdx.x * 256 + threadIdx.x;
    if (i >= N_PTS) return;
    int l = labels[i];
    int pos = atomicAdd(&g_cur[l], 1) + g_bsum[l >> 10];
    g_slbl[pos] = l;
    float4 v0 = ((const float4*)pf)[(size_t)i * 2];
    float4 v1 = ((const float4*)pf)[(size_t)i * 2 + 1];
    float d0 = cc[(size_t)l * 3 + 0] - pts[(size_t)i * 3 + 0];
    float d1 = cc[(size_t)l * 3 + 1] - pts[(size_t)i * 3 + 1];
    float d2 = cc[(size_t)l * 3 + 2] - pts[(size_t)i * 3 + 2];
    uint4* dst = (uint4*)(g_xh + (size_t)pos * 16);
    dst[0] = make_uint4(h2u(v0.x, v0.y), h2u(v0.z, v0.w),
                        h2u(v1.x, v1.y), h2u(v1.z, v1.w));
    dst[1] = make_uint4(h2u(d0, d1), h2u(d2, 0.f), 0u, 0u);
}

// ---------------------------------------------------------------------------
// k_point: tensor-core MLP, TWO groups interleaved per iteration for mma ILP.
// Large B-fragments in block-shared memory (no spills). GRP=8 (R14 config).
// ---------------------------------------------------------------------------
__global__ __launch_bounds__(256, 2) void k_point(
    const float* __restrict__ we0, const float* __restrict__ be0,
    const float* __restrict__ we1, const float* __restrict__ be1,
    const float* __restrict__ we2, const float* __restrict__ be2,
    const float* __restrict__ we3, const float* __restrict__ be3,
    const float* __restrict__ wa0, const float* __restrict__ ba0,
    const float* __restrict__ wa1, const float* __restrict__ ba1)
{
    __shared__ float stp[WPB][16 * 72];
    __shared__ int   slb[WPB][32];
    __shared__ __align__(16) uint2 sBA[8][32];
    __shared__ __align__(16) uint2 sL3a[8][32];
    __shared__ __align__(16) uint2 sL3b[8][32];

    const int lane = threadIdx.x & 31;
    const int wid  = threadIdx.x >> 5;
    const int g    = lane >> 2;
    const int k0   = (lane & 3) * 2;

    float* W = stp[wid];

    if (wid == 0) {
#pragma unroll
        for (int t = 0; t < 8; t++) {
            int n = t * 8 + g;
            sBA[t][lane] = make_uint2(
                h2u(wa0[k0 * 64 + n], wa0[(k0 + 1) * 64 + n]),
                h2u(k0 + 8 < 11 ? wa0[(k0 + 8) * 64 + n] : 0.f,
                    k0 + 9 < 11 ? wa0[(k0 + 9) * 64 + n] : 0.f));
            sL3a[t][lane] = make_uint2(
                h2u(we3[k0 * 64 + n],       we3[(k0 + 1) * 64 + n]),
                h2u(we3[(k0 + 8) * 64 + n], we3[(k0 + 9) * 64 + n]));
            sL3b[t][lane] = make_uint2(
                h2u(we3[(k0 + 16) * 64 + n], we3[(k0 + 17) * 64 + n]),
                h2u(we3[(k0 + 24) * 64 + n], we3[(k0 + 25) * 64 + n]));
        }
    }

    uint32_t bE0[2];
    {
        int n = g;
        bE0[0] = h2u(we0[k0 * 8 + n], we0[(k0 + 1) * 8 + n]);
        bE0[1] = h2u(k0 + 8 < 11 ? we0[(k0 + 8) * 8 + n] : 0.f,
                     k0 + 9 < 11 ? we0[(k0 + 9) * 8 + n] : 0.f);
    }
    uint32_t bE1[2];
#pragma unroll
    for (int t = 0; t < 2; t++) {
        int n = t * 8 + g;
        bE1[t] = h2u(we1[k0 * 16 + n], we1[(k0 + 1) * 16 + n]);
    }
    uint32_t bE2[4][2];
#pragma unroll
    for (int t = 0; t < 4; t++) {
        int n = t * 8 + g;
        bE2[t][0] = h2u(we2[k0 * 32 + n], we2[(k0 + 1) * 32 + n]);
        bE2[t][1] = h2u(we2[(k0 + 8) * 32 + n], we2[(k0 + 9) * 32 + n]);
    }
    const float ba1s = ba1[0];
    __syncthreads();

    const int grp0 = (blockIdx.x * WPB + wid) * GRP;

#pragma unroll 1
    for (int it = 0; it < GRP; it += 2) {
        const int grpA = grp0 + it;
        const bool vA = (grpA < N_GRPS);
        const bool vB = (grpA + 1 < N_GRPS);
        if (!vA) break;
        const int pos0 = grpA * 16;

        __syncwarp();
        {
            int src = pos0 + lane;
            slb[wid][lane] = g_slbl[vB ? src : (lane < 16 ? src : pos0)];
        }

        uint32_t axA[4], axB[4];
        {
            const __half* r1 = g_xh + (size_t)(pos0 + g) * 16;
            const __half* r2 = g_xh + (size_t)(pos0 + g + 8) * 16;
            axA[0] = *(const uint32_t*)(r1 + k0);
            axA[1] = *(const uint32_t*)(r2 + k0);
            axA[2] = *(const uint32_t*)(r1 + k0 + 8);
            axA[3] = *(const uint32_t*)(r2 + k0 + 8);
            const size_t offB = vB ? 16 : 0;
            const __half* r3 = g_xh + (size_t)(pos0 + offB + g) * 16;
            const __half* r4 = g_xh + (size_t)(pos0 + offB + g + 8) * 16;
            axB[0] = *(const uint32_t*)(r3 + k0);
            axB[1] = *(const uint32_t*)(r4 + k0);
            axB[2] = *(const uint32_t*)(r3 + k0 + 8);
            axB[3] = *(const uint32_t*)(r4 + k0 + 8);
        }
        __syncwarp();

        // ----- attention (both groups interleaved) -----
        float aaA = 0.f, abA = 0.f, aaB = 0.f, abB = 0.f;
#pragma unroll
        for (int t = 0; t < 8; t++) {
            float b0 = ba0[t * 8 + k0], b1v = ba0[t * 8 + k0 + 1];
            float dA[4] = {b0, b1v, b0, b1v};
            float dB[4] = {b0, b1v, b0, b1v};
            uint2 bb = sBA[t][lane];
            mma16816_acc(dA, axA, (const uint32_t*)&bb);
            mma16816_acc(dB, axB, (const uint32_t*)&bb);
            float w0 = wa1[t * 8 + k0], w1 = wa1[t * 8 + k0 + 1];
            aaA += fmaxf(dA[0], 0.f) * w0 + fmaxf(dA[1], 0.f) * w1;
            abA += fmaxf(dA[2], 0.f) * w0 + fmaxf(dA[3], 0.f) * w1;
            aaB += fmaxf(dB[0], 0.f) * w0 + fmaxf(dB[1], 0.f) * w1;
            abB += fmaxf(dB[2], 0.f) * w0 + fmaxf(dB[3], 0.f) * w1;
        }
        aaA += __shfl_xor_sync(0xffffffffu, aaA, 1);
        aaA += __shfl_xor_sync(0xffffffffu, aaA, 2);
        abA += __shfl_xor_sync(0xffffffffu, abA, 1);
        abA += __shfl_xor_sync(0xffffffffu, abA, 2);
        aaB += __shfl_xor_sync(0xffffffffu, aaB, 1);
        aaB += __shfl_xor_sync(0xffffffffu, aaB, 2);
        abB += __shfl_xor_sync(0xffffffffu, abB, 1);
        abB += __shfl_xor_sync(0xffffffffu, abB, 2);
        const float aA0 = 1.f / (1.f + __expf(-(aaA + ba1s)));
        const float aA1 = 1.f / (1.f + __expf(-(abA + ba1s)));
        const float aB0 = 1.f / (1.f + __expf(-(aaB + ba1s)));
        const float aB1 = 1.f / (1.f + __expf(-(abB + ba1s)));

        // ----- L0 -----
        uint32_t h0A[2], h0B[2];
        {
            float b0 = be0[k0], b1v = be0[k0 + 1];
            float dA[4] = {b0, b1v, b0, b1v};
            float dB[4] = {b0, b1v, b0, b1v};
            mma16816_acc(dA, axA, bE0);
            mma16816_acc(dB, axB, bE0);
            h0A[0] = h2u(fmaxf(dA[0], 0.f), fmaxf(dA[1], 0.f));
            h0A[1] = h2u(fmaxf(dA[2], 0.f), fmaxf(dA[3], 0.f));
            h0B[0] = h2u(fmaxf(dB[0], 0.f), fmaxf(dB[1], 0.f));
            h0B[1] = h2u(fmaxf(dB[2], 0.f), fmaxf(dB[3], 0.f));
        }
        // ----- L1 -----
        uint32_t h1A[4], h1B[4];
#pragma unroll
        for (int t = 0; t < 2; t++) {
            float b0 = be1[t * 8 + k0], b1v = be1[t * 8 + k0 + 1];
            float dA[4] = {b0, b1v, b0, b1v};
            float dB[4] = {b0, b1v, b0, b1v};
            mma1688_acc(dA, h0A, bE1[t]);
            mma1688_acc(dB, h0B, bE1[t]);
            h1A[t * 2 + 0] = h2u(fmaxf(dA[0], 0.f), fmaxf(dA[1], 0.f));
            h1A[t * 2 + 1] = h2u(fmaxf(dA[2], 0.f), fmaxf(dA[3], 0.f));
            h1B[t * 2 + 0] = h2u(fmaxf(dB[0], 0.f), fmaxf(dB[1], 0.f));
            h1B[t * 2 + 1] = h2u(fmaxf(dB[2], 0.f), fmaxf(dB[3], 0.f));
        }
        // ----- L2 -----
        uint32_t h2aA[4], h2bA[4], h2aB[4], h2bB[4];
#pragma unroll
        for (int t = 0; t < 4; t++) {
            float b0 = be2[t * 8 + k0], b1v = be2[t * 8 + k0 + 1];
            float dA[4] = {b0, b1v, b0, b1v};
            float dB[4] = {b0, b1v, b0, b1v};
            mma16816_acc(dA, h1A, bE2[t]);
            mma16816_acc(dB, h1B, bE2[t]);
            uint32_t loA = h2u(fmaxf(dA[0], 0.f), fmaxf(dA[1], 0.f));
            uint32_t hiA = h2u(fmaxf(dA[2], 0.f), fmaxf(dA[3], 0.f));
            uint32_t loB = h2u(fmaxf(dB[0], 0.f), fmaxf(dB[1], 0.f));
            uint32_t hiB = h2u(fmaxf(dB[2], 0.f), fmaxf(dB[3], 0.f));
            if (t == 0)      { h2aA[0] = loA; h2aA[1] = hiA; h2aB[0] = loB; h2aB[1] = hiB; }
            else if (t == 1) { h2aA[2] = loA; h2aA[3] = hiA; h2aB[2] = loB; h2aB[3] = hiB; }
            else if (t == 2) { h2bA[0] = loA; h2bA[1] = hiA; h2bB[0] = loB; h2bB[1] = hiB; }
            else             { h2bA[2] = loA; h2bA[3] = hiA; h2bB[2] = loB; h2bB[3] = hiB; }
        }

        // ----- L3 + epilogue, group A then group B (W reused) -----
#pragma unroll 1
        for (int q = 0; q < 2; q++) {
            const uint32_t* h2a = q ? h2aB : h2aA;
            const uint32_t* h2b = q ? h2bB : h2bA;
            const float s0 = q ? aB0 : aA0;
            const float s1 = q ? aB1 : aA1;
            if (q && !vB) break;

#pragma unroll
            for (int t = 0; t < 8; t++) {
                float b0 = be3[t * 8 + k0], b1v = be3[t * 8 + k0 + 1];
                float d[4] = {b0, b1v, b0, b1v};
                uint2 wa = sL3a[t][lane];
                uint2 wb = sL3b[t][lane];
                mma16816_acc(d, h2a, (const uint32_t*)&wa);
                mma16816_acc(d, h2b, (const uint32_t*)&wb);
                float v0 = fmaxf(d[0], 0.f) * s0;
                float v1 = fmaxf(d[1], 0.f) * s0;
                float v2 = fmaxf(d[2], 0.f) * s1;
                float v3 = fmaxf(d[3], 0.f) * s1;
                *(float2*)(W + g * 72 + t * 8 + k0)       = make_float2(v0, v1);
                *(float2*)(W + (g + 8) * 72 + t * 8 + k0) = make_float2(v2, v3);
            }
            __syncwarp();

            {
                const int c0 = 2 * lane;
                const int lb0 = q * 16;
                int cur = slb[wid][lb0];
                float2 s = *(const float2*)(W + c0);
#pragma unroll 1
                for (int p = 1; p < 16; p++) {
                    int lb = slb[wid][lb0 + p];
                    float2 v = *(const float2*)(W + p * 72 + c0);
                    if (lb == cur) { s.x += v.x; s.y += v.y; }
                    else {
                        red2(g_agg + (size_t)cur * 64 + c0, s.x, s.y);
                        cur = lb; s = v;
                    }
                }
                red2(g_agg + (size_t)cur * 64 + c0, s.x, s.y);
            }
            __syncwarp();
        }
    }
}

// ---------------------------------------------------------------------------
// k_mid (tensor, smem-staged) — R14 version.
// ---------------------------------------------------------------------------
__global__ __launch_bounds__(256) void k_mid(
    const float* __restrict__ wo0, const float* __restrict__ bo0)
{
    __shared__ __align__(16) __half woT[128 * 68];
    __shared__ __align__(16) __half aH[128 * 68];
    __shared__ float sb[128];

    const int t = threadIdx.x;
    for (int i = t; i < 8192; i += 256) {
        int k = i >> 7, n = i & 127;
        woT[n * 68 + k] = __float2half(wo0[i]);
    }
    if (t < 128) sb[t] = bo0[t];
    const size_t base = (size_t)blockIdx.x * 128;
    for (int i = t; i < 8192; i += 256) {
        int row = i >> 6, k = i & 63;
        aH[row * 68 + k] = __float2half(g_agg[base * 64 + i]);
    }
    __syncthreads();

    const int lane = t & 31, w = t >> 5;
    const int g  = lane >> 2;
    const int k0 = (lane & 3) * 2;
    const int rA = w * 16 + g, rB = rA + 8;

    uint32_t a[4][4];
#pragma unroll
    for (int kk = 0; kk < 4; kk++) {
        a[kk][0] = *(const uint32_t*)(aH + rA * 68 + kk * 16 + k0);
        a[kk][1] = *(const uint32_t*)(aH + rB * 68 + kk * 16 + k0);
        a[kk][2] = *(const uint32_t*)(aH + rA * 68 + kk * 16 + k0 + 8);
        a[kk][3] = *(const uint32_t*)(aH + rB * 68 + kk * 16 + k0 + 8);
    }

#pragma unroll
    for (int tt = 0; tt < 16; tt++) {
        const int n = tt * 8;
        float b0 = sb[n + k0], b1 = sb[n + k0 + 1];
        float d[4] = {b0, b1, b0, b1};
#pragma unroll
        for (int kk = 0; kk < 4; kk++) {
            uint32_t bb[2];
            bb[0] = *(const uint32_t*)(woT + (n + g) * 68 + kk * 16 + k0);
            bb[1] = *(const uint32_t*)(woT + (n + g) * 68 + kk * 16 + k0 + 8);
            mma16816_acc(d, a[kk], bb);
        }
        *(uint32_t*)(g_midh + (base + rA) * 128 + n + k0) = h2u(fmaxf(d[0], 0.f), fmaxf(d[1], 0.f));
        *(uint32_t*)(g_midh + (base + rB) * 128 + n + k0) = h2u(fmaxf(d[2], 0.f), fmaxf(d[3], 0.f));
    }
}

// ---------------------------------------------------------------------------
// k_out (tensor, smem-staged) — R14 version.
// ---------------------------------------------------------------------------
__global__ __launch_bounds__(256) void k_out(
    const float* __restrict__ wo1, const float* __restrict__ bo1,
    float* __restrict__ out)
{
    extern __shared__ __align__(16) __half sh[];
    __half* aH  = sh;
    __half* woT = sh + 128 * 136;

    const int t  = threadIdx.x;
    const int mg = blockIdx.x >> 2;
    const int nb = (blockIdx.x & 3) * 64;
    const size_t base = (size_t)mg * 128;

    const uint32_t* gm32 = (const uint32_t*)(g_midh + base * 128);
    for (int i = t; i < 8192; i += 256) {
        int row = i >> 6, kp = i & 63;
        ((uint32_t*)(aH + row * 136))[kp] = gm32[i];
    }
    for (int i = t; i < 8192; i += 256) {
        int k = i >> 6, n = i & 63;
        woT[n * 136 + k] = __float2half(wo1[k * 256 + nb + n]);
    }
    __syncthreads();

    const int lane = t & 31, w = t >> 5;
    const int g  = lane >> 2;
    const int k0 = (lane & 3) * 2;
    const int rA = w * 16 + g, rB = rA + 8;

    uint32_t a[8][4];
#pragma unroll
    for (int kk = 0; kk < 8; kk++) {
        a[kk][0] = *(const uint32_t*)(aH + rA * 136 + kk * 16 + k0);
        a[kk][1] = *(const uint32_t*)(aH + rB * 136 + kk * 16 + k0);
        a[kk][2] = *(const uint32_t*)(aH + rA * 136 + kk * 16 + k0 + 8);
        a[kk][3] = *(const uint32_t*)(aH + rB * 136 + kk * 16 + k0 + 8);
    }

#pragma unroll
    for (int tt = 0; tt < 8; tt++) {
        const int n = tt * 8;
        float2 bb2 = *(const float2*)(bo1 + nb + n + k0);
        float d[4] = {bb2.x, bb2.y, bb2.x, bb2.y};
#pragma unroll
        for (int kk = 0; kk < 8; kk++) {
            uint32_t f[2];
            f[0] = *(const uint32_t*)(woT + (n + g) * 136 + kk * 16 + k0);
            f[1] = *(const uint32_t*)(woT + (n + g) * 136 + kk * 16 + k0 + 8);
            mma16816_acc(d, a[kk], f);
        }
        *(float2*)(out + (base + rA) * 256 + nb + n + k0) = make_float2(fmaxf(d[0], 0.f), fmaxf(d[1], 0.f));
        *(float2*)(out + (base + rB) * 256 + nb + n + k0) = make_float2(fmaxf(d[2], 0.f), fmaxf(d[3], 0.f));
    }
}

// ---------------------------------------------------------------------------
extern "C" void kernel_launch(void* const* d_in, const int* in_sizes, int n_in,
                              void* d_out, int out_size)
{
    const float* pf     = (const float*)d_in[0];
    const int*   labels = (const int*)  d_in[1];
    const float* cc     = (const float*)d_in[2];
    const float* pts    = (const float*)d_in[3];
    const float* we0    = (const float*)d_in[4];
    const float* be0    = (const float*)d_in[5];
    const float* we1    = (const float*)d_in[6];
    const float* be1    = (const float*)d_in[7];
    const float* we2    = (const float*)d_in[8];
    const float* be2    = (const float*)d_in[9];
    const float* we3    = (const float*)d_in[10];
    const float* be3    = (const float*)d_in[11];
    const float* wa0    = (const float*)d_in[12];
    const float* ba0    = (const float*)d_in[13];
    const float* wa1    = (const float*)d_in[14];
    const float* ba1    = (const float*)d_in[15];
    const float* wo0    = (const float*)d_in[16];
    const float* bo0    = (const float*)d_in[17];
    const float* wo1    = (const float*)d_in[18];
    const float* bo1    = (const float*)d_in[19];
    float* out = (float*)d_out;

    const int smem_out = (128 * 136 + 64 * 136) * 2;
    static int attr_set = 0;
    if (!attr_set) {
        cudaFuncSetAttribute(k_out, cudaFuncAttributeMaxDynamicSharedMemorySize, smem_out);
        attr_set = 1;
    }

    k_zero<<<(ZAGG4 + ZCNT4 + 255) / 256, 256>>>();
    k_hist<<<(N_PTS + 255) / 256, 256>>>(labels);
    k_scan1<<<64, 256>>>();
    k_scan2<<<1, 64>>>();
    k_scatter<<<(N_PTS + 255) / 256, 256>>>(pf, pts, cc, labels);
    k_point<<<PT_BLOCKS, 256>>>(we0, be0, we1, be1, we2, be2, we3, be3,
                                wa0, ba0, wa1, ba1);
    k_mid<<<N_CLU / 128, 256>>>(wo0, bo0);
    k_out<<<(N_CLU / 128) * 4, 256, smem_out>>>(wo1, bo1, out);
}